// round 2
// baseline (speedup 1.0000x reference)
#include <cuda_runtime.h>
#include <cuda_bf16.h>

// B=16, C=128, H=W=224, KS=3, STRIDE=2, ALPHA=16 -> h[z] = -(z/t)^16; Ho=Wo=111.
#define B_  16
#define C_  128
#define H_  224
#define W_  224
#define HO_ 111
#define WO_ 111
#define TR  8                       // output rows per block
#define IN_ROWS (2*TR + 1)          // 17 input rows per tile

__global__ __launch_bounds__(128)
void lfp_kernel(const float* __restrict__ f,
                const float* __restrict__ t,
                float* __restrict__ out)
{
    __shared__ float s[IN_ROWS][W_];          // 17*224*4 = 15232 B

    const int tid = threadIdx.x;
    const int bc  = blockIdx.z;               // b*C + c
    const int c   = bc & (C_ - 1);
    const int i0  = blockIdx.y * TR;          // first output row of tile
    const int r0  = 2 * i0;                   // first input row of tile

    // ---- Stage 1: coalesced float4 load of the input tile ----
    const float* __restrict__ fb = f + (size_t)bc * (H_ * W_);
    float4* s4 = (float4*)&s[0][0];
    #pragma unroll 4
    for (int k = tid; k < IN_ROWS * (W_ / 4); k += 128) {
        const int lr = k / (W_ / 4);
        const int lc = k - lr * (W_ / 4);
        int gr = r0 + lr;
        if (gr > H_ - 1) gr = H_ - 1;         // clamp (clamped rows never used)
        s4[k] = ((const float4*)(fb + (size_t)gr * W_))[lc];
    }
    __syncthreads();

    // ---- Stage 2: compute from smem ----
    const int j = tid;                        // output column
    if (j >= WO_) return;

    // Per-channel: h0 = 0, h1 = -(1/t)^16, h2 = -(2/t)^16
    const float inv = 1.0f / __ldg(t + c);
    const float x2  = inv * inv;
    const float x4  = x2 * x2;
    const float x8  = x4 * x4;
    const float x16 = x8 * x8;
    const float h1  = -x16;
    const float h2  = -65536.0f * x16;

    float* __restrict__ ob = out + (size_t)bc * (HO_ * WO_);
    int iend = i0 + TR;
    if (iend > HO_) iend = HO_;

    // Per input row r: center c_j = row[2j+1], edge e_j = max(row[2j], row[2j+2])
    // Read as float2[j] (cols 2j,2j+1) + float2[j+1].x (col 2j+2): conflict-free LDS.64.
    {
        const float2* p0 = (const float2*)s[0];
        float2 a0 = p0[j];
        float  b0 = p0[j + 1].x;
        float  cc0 = a0.y, ee0 = fmaxf(a0.x, b0);

        #pragma unroll
        for (int ii = 0; ii < TR; ++ii) {
            const int i = i0 + ii;
            if (i >= iend) break;
            const int lr = 2 * ii;
            const float2* p1 = (const float2*)s[lr + 1];
            const float2* p2 = (const float2*)s[lr + 2];
            float2 a1 = p1[j];  float b1 = p1[j + 1].x;
            float2 a2 = p2[j];  float b2 = p2[j + 1].x;
            float cc1 = a1.y, ee1 = fmaxf(a1.x, b1);
            float cc2 = a2.y, ee2 = fmaxf(a2.x, b2);

            float v = cc1;
            v = fmaxf(v, ee1 + h1);
            v = fmaxf(v, fmaxf(cc0, cc2) + h1);
            v = fmaxf(v, fmaxf(ee0, ee2) + h2);
            ob[(size_t)i * WO_ + j] = v;

            cc0 = cc2; ee0 = ee2;
        }
    }
}

extern "C" void kernel_launch(void* const* d_in, const int* in_sizes, int n_in,
                              void* d_out, int out_size)
{
    const float* f = (const float*)d_in[0];
    const float* t = (const float*)d_in[1];
    float* out = (float*)d_out;

    dim3 block(128, 1, 1);
    dim3 grid(1, (HO_ + TR - 1) / TR, B_ * C_);
    lfp_kernel<<<grid, block>>>(f, t, out);
}